// round 17
// baseline (speedup 1.0000x reference)
#include <cuda_runtime.h>
#include <cuda_bf16.h>
#include <cstdint>

#define B_   16
#define C_   192
#define TX_  512
#define TY_  2048
#define SEG_ 32
#define K2_  384          // 2*C
#define NEG_INF_ (-1e9f)
#define CH_  16           // DP chunk rows staged in smem per phase
#define NLOAD_ 480        // dp loader lanes (15 warps)

// grid layout of fused kernel
#define PREP0_   (B_)                  // 16
#define NPREP_   192                   // 12 per batch
#define CVEC0_   (PREP0_ + NPREP_)     // 208
#define ZSL0_    (CVEC0_ + B_)         // 224
#define GEMMS_   (ZSL0_ + B_)          // 240
#define NGEMM_   512                   // CTAs; halves pull 1024 tiles from a queue
#define NTILE_   1024                  // 4 nb x 16 b x 16 mblk
#define EPIS_    (GEMMS_ + NGEMM_)     // 752
#define NEPI_    (B_ * 64)             // 1024
#define NCTAS_   (EPIS_ + NEPI_)       // 1776

// dynamic smem: dp CTA -> dirs(128KB)+rowbuf(64KB); gemm CTA -> 2 x (As+Bs)(32KB each)
#define FUSED_SMEM (TY_ * 32 * 2 + 2 * CH_ * 128 * 16)

// ---------------- scratch (device globals: no runtime allocation) ----------------
__device__ float g_B[B_ * K2_ * TX_];
__device__ float g_cvec[B_ * TX_];
__device__ float g_negcent[(size_t)B_ * TY_ * TX_];  // 64 MB
__device__ int   g_idx[B_ * TY_];
__device__ int   g_cnt[B_ * 16];     // per (b, 128-row band) completed n-tiles (target 4)
__device__ int   g_prep[B_];         // prep(12) + cvec(1) done (target 13)
__device__ int   g_btp[B_];          // backtrack rows finalized from top (1=presets done .. t_y=all)
__device__ int   g_epicnt[B_];       // finished epilogue CTAs (target 64; 64th resets flags)
__device__ int   g_gemmq;            // gemm tile queue head (reset by prep CTA 0 in wave 1)

// ---------------- helpers ----------------
union F2 { float2 f; unsigned long long u; };

__device__ __forceinline__ unsigned long long ffma2(unsigned long long a,
                                                    unsigned long long b,
                                                    unsigned long long c) {
    unsigned long long d;
    asm("fma.rn.f32x2 %0, %1, %2, %3;" : "=l"(d) : "l"(a), "l"(b), "l"(c));
    return d;
}

__device__ __forceinline__ int ld_acq(const int* p) {
    int v;
    asm volatile("ld.acquire.gpu.global.b32 %0, [%1];" : "=r"(v) : "l"(p) : "memory");
    return v;
}
__device__ __forceinline__ void st_rel(int* p, int v) {
    asm volatile("st.release.gpu.global.b32 [%0], %1;" :: "l"(p), "r"(v) : "memory");
}

#define CP_ASYNC16(smem_u32, gptr) \
    asm volatile("cp.async.cg.shared.global [%0], [%1], 16;" :: "r"(smem_u32), "l"(gptr) : "memory")
#define CP_COMMIT() asm volatile("cp.async.commit_group;" ::: "memory")
#define CP_WAIT0()  asm volatile("cp.async.wait_group 0;" ::: "memory")
#define HBAR(id)    asm volatile("bar.sync %0, 256;" :: "r"(id) : "memory")

// ---------------- fused: prep + cvec + zslice + queued GEMM + DP + gated epilogues ----------------
#define BM 128
#define BN 128
#define BK 16

// DP row update; direction bit = sign of (v[j] - v[j-1]).
__device__ __forceinline__ void dp_row(float4 (&cur)[4], float (&v)[16],
                                       unsigned short* dirs, int t, int lane)
{
    float sh = __shfl_up_sync(0xffffffffu, v[15], 1);
    float left0 = (lane == 0) ? NEG_INF_ : sh;

    float r[16];
    r[0]=cur[0].x;  r[1]=cur[0].y;  r[2]=cur[0].z;  r[3]=cur[0].w;
    r[4]=cur[1].x;  r[5]=cur[1].y;  r[6]=cur[1].z;  r[7]=cur[1].w;
    r[8]=cur[2].x;  r[9]=cur[2].y;  r[10]=cur[2].z; r[11]=cur[2].w;
    r[12]=cur[3].x; r[13]=cur[3].y; r[14]=cur[3].z; r[15]=cur[3].w;

    unsigned bits = 0u;
#pragma unroll
    for (int j = 15; j >= 1; j--) {
        float left = v[j - 1];
        float d = v[j] - left;                     // sign=1 <=> left > v[j]
        bits |= (__float_as_uint(d) >> (31 - j)) & (1u << j);
        v[j] = r[j] + fmaxf(left, v[j]);
    }
    float d0 = v[0] - left0;
    bits |= (__float_as_uint(d0) >> 31);
    v[0] = r[0] + fmaxf(left0, v[0]);

    dirs[t * 32 + lane] = (unsigned short)bits;
}

__global__ void __launch_bounds__(512) fused_kernel(const float* __restrict__ z_p,
                                                    const float* __restrict__ m_p,
                                                    const float* __restrict__ logs_p,
                                                    const float* __restrict__ z,
                                                    const int* __restrict__ x_lengths,
                                                    const int* __restrict__ y_lengths,
                                                    const float* __restrict__ rand_u,
                                                    float* __restrict__ out_z,
                                                    float* __restrict__ out_ids,
                                                    float* __restrict__ out_attn,
                                                    float* __restrict__ out_m,
                                                    float* __restrict__ out_l)
{
    extern __shared__ char sdyn[];
    __shared__ int s_tile[2];
    const int tid = threadIdx.x;
    const unsigned bid = blockIdx.x;

    if (bid < PREP0_) {
        // ================= DP consumer CTA (batch b): 1 compute warp + 15 loaders =================
        unsigned short* dirs = (unsigned short*)sdyn;                      // [TY_][32]
        float4* rowbuf = (float4*)(sdyn + (size_t)TY_ * 32 * 2);           // [2][CH_][128]

        const int b    = bid;
        const int lane = tid & 31;
        const int w    = tid >> 5;                                         // 0..15
        const int t_x  = min(x_lengths[b], TX_);
        const int t_y  = min(y_lengths[b], TY_);
        const int nch  = (t_y + CH_ - 1) / CH_;                            // <= 128 (16-row chunks)

        const float4* src = (const float4*)(g_negcent + (size_t)b * TY_ * TX_);
        const uint32_t rb_u32 = (uint32_t)__cvta_generic_to_shared(rowbuf);
        const int* cntb = g_cnt + b * 16;

        // ---- loader prologue: wait band 0 (rows 0..127), stream chunk 0 ----
        if (w > 0) {
            if (lane == 0) while (ld_acq(&cntb[0]) < 4) { }
            __syncwarp();
            const int lid = tid - 32;                                      // 0..479
            for (int p = lid; p < CH_ * 128; p += NLOAD_)
                CP_ASYNC16(rb_u32 + p * 16, src + (size_t)(p >> 7) * 128 + (p & 127));
            CP_COMMIT();
            CP_WAIT0();
        }

        float v[16];
#pragma unroll
        for (int j = 0; j < 16; j++) v[j] = NEG_INF_;
        if (tid == 0) v[0] = 0.0f;
        __syncthreads();

        for (int k = 0; k < nch; k++) {
            if (w > 0) {
                if (k + 1 < nch) {
                    const int c = k + 1;
                    if ((c & 7) == 0) {                                    // new 128-row band
                        if (lane == 0) while (ld_acq(&cntb[c >> 3]) < 4) { }
                        __syncwarp();
                    }
                    const int lid = tid - 32;
                    const int t0 = c * CH_;
                    const uint32_t dstb = rb_u32 + (uint32_t)((c & 1) * CH_ * 128 * 16);
                    for (int p = lid; p < CH_ * 128; p += NLOAD_)
                        CP_ASYNC16(dstb + p * 16, src + (size_t)(t0 + (p >> 7)) * 128 + (p & 127));
                    CP_COMMIT();
                    CP_WAIT0();
                }
            } else {
                const float4* bufb = rowbuf + (k & 1) * CH_ * 128 + lane * 4;
                const int tb = k * CH_;
                float4 cur[4], nxt[4];
                cur[0] = bufb[0]; cur[1] = bufb[1]; cur[2] = bufb[2]; cur[3] = bufb[3];
#pragma unroll
                for (int r = 0; r < CH_ - 1; r++) {
                    const float4* pn = bufb + (r + 1) * 128;
                    nxt[0] = pn[0]; nxt[1] = pn[1]; nxt[2] = pn[2]; nxt[3] = pn[3];
                    dp_row(cur, v, dirs, tb + r, lane);
                    cur[0] = nxt[0]; cur[1] = nxt[1]; cur[2] = nxt[2]; cur[3] = nxt[3];
                }
                dp_row(cur, v, dirs, tb + CH_ - 1, lane);
            }
            __syncthreads();
        }

        // rows >= t_y: no path (preset before any publish)
        for (int t = t_y + tid; t < TY_; t += 512) g_idx[b * TY_ + t] = -1;
        __syncthreads();

        // backtrack (single lane) with speculative word prefetch + progressive publish
        if (tid == 0) {
            __threadfence();
            st_rel(&g_btp[b], 1);                                          // presets visible

            const int base = b * TY_;
            int idx = t_x - 1;
            unsigned w0, w1;
            unsigned wv = dirs[(t_y - 1) * 32 + (idx >> 4)];
            for (int j = t_y - 1; j > 0; j--) {
                g_idx[base + j] = idx;
                const int idxm = (idx > 0) ? idx - 1 : 0;
                w0 = dirs[(j - 1) * 32 + (idx >> 4)];                      // spec: bit=0 word
                w1 = dirs[(j - 1) * 32 + (idxm >> 4)];                     // spec: bit=1 word
                unsigned bit = (wv >> (idx & 15)) & 1u;
                idx -= (int)bit;
                wv = bit ? w1 : w0;
                if ((j & 255) == 0) { __threadfence(); st_rel(&g_btp[b], t_y - j); }
            }
            g_idx[base] = idx;
            __threadfence();
            st_rel(&g_btp[b], t_y);                                        // all rows final
        }
        return;
    }

    if (bid < CVEC0_) {
        // ================= prep CTA: build g_B slice for batch b =================
        const int pi  = bid - PREP0_;
        if (pi == 0 && tid == 0) atomicExch(&g_gemmq, 0);   // wave-1 reset, before any gemm CTA exists
        const int b   = pi / 12;
        const int sub = pi % 12;
        const int e0  = sub * 8192;                 // of C_*TX_ = 98304 elements
#pragma unroll
        for (int i = 0; i < 16; i++) {
            int e = e0 + tid + i * 512;
            int c = e >> 9;                          // /512
            int s = e & 511;
            int off = (b * C_ + c) * TX_ + s;
            float lg = logs_p[off];
            float mp = m_p[off];
            float se = expf(-2.0f * lg);
            g_B[(b * K2_ + c) * TX_ + s]      = se;
            g_B[(b * K2_ + C_ + c) * TX_ + s] = se * mp;
        }
        __syncthreads();
        if (tid == 0) { __threadfence(); atomicAdd(&g_prep[b], 1); }
        return;
    }

    if (bid < ZSL0_) {
        // ================= cvec CTA: per-column constant for batch b =================
        const int b = bid - CVEC0_;
        const int s = tid;                           // 512 columns
        float acc = 0.f;
        for (int c = 0; c < C_; c++) {
            int off = (b * C_ + c) * TX_ + s;
            float lg = logs_p[off];
            float mp = m_p[off];
            float se = expf(-2.0f * lg);
            acc += -0.5f * se * mp * mp - lg;
        }
        g_cvec[b * TX_ + s] = acc;
        __syncthreads();
        if (tid == 0) { __threadfence(); atomicAdd(&g_prep[b], 1); }
        return;
    }

    if (bid < GEMMS_) {
        // ================= zslice CTA (one per batch, no dependencies) =================
        const int b = bid - ZSL0_;
        int safe  = min(y_lengths[b], TY_);
        int idmax = max(safe - SEG_, 0);
        int ids   = (int)(rand_u[b] * ((float)idmax + 1e-8f));
        if (tid == 0) out_ids[b] = (float)ids;
#pragma unroll
        for (int i = 0; i < 12; i++) {
            int p = tid + i * 512;
            int k = p & (SEG_ - 1);
            int c = p >> 5;
            float vv = z[(b * C_ + c) * TY_ + ids + k];
            out_z[(b * C_ + c) * SEG_ + k] = (k < safe - ids) ? vv : 0.f;
        }
        return;
    }

    if (bid < EPIS_) {
        // ======== GEMM producer CTA: two independent halves pulling tiles from a queue ========
        const int half = tid >> 8;                // 0 or 1
        const int htid = tid & 255;
        const int barid = 1 + half;

        typedef float TileT[BK][BM];
        TileT* As = (TileT*)(sdyn + half * 32768);               // [2][16][128] 16KB
        TileT* Bs = (TileT*)(sdyn + half * 32768 + 16384);       // [2][16][128] 16KB

        for (;;) {
            if (htid == 0) s_tile[half] = atomicAdd(&g_gemmq, 1);
            HBAR(barid);
            const int id = s_tile[half];
            if (id >= NTILE_) break;

            const int nb   = id & 3;                  // 4 n-blocks
            const int b    = (id >> 2) & 15;          // 16 batches
            const int mblk = id >> 6;                 // 16 m-blocks (low bands first)
            const int m0   = mblk * BM;
            const int n0   = nb * BN;

            // gate on prep+cvec of this batch (12 + 1); also separates s_tile read from next write
            if (htid == 0) { while (ld_acq(&g_prep[b]) < 13) { } }
            HBAR(barid);

            const bool active = (m0 < y_lengths[b]) && (n0 < x_lengths[b]);

            if (active) {
                const int kRow  = htid >> 4;              // 0..15
                const int lbase = (htid & 15) << 3;       // 0..120
                const int mBase = (htid >> 4) << 3;       // 8 rows
                const int nBase = (htid & 15) << 3;       // 8 cols

                const float* zpb = z_p + b * C_ * TY_;
                const float* Bb  = g_B + b * K2_ * TX_;

                F2 acc[8][4];
#pragma unroll
                for (int i = 0; i < 8; i++)
#pragma unroll
                    for (int j = 0; j < 4; j++) { acc[i][j].f.x = 0.f; acc[i][j].f.y = 0.f; }

                float4 ra0, ra1, rb0, rb1;
                {
                    int kk = kRow;
                    int cA = (kk < C_) ? kk : kk - C_;
                    const float* pA = zpb + cA * TY_ + m0 + lbase;
                    ra0 = *(const float4*)pA;
                    ra1 = *(const float4*)(pA + 4);
                    if (kk < C_) {
                        ra0.x = -0.5f * ra0.x * ra0.x; ra0.y = -0.5f * ra0.y * ra0.y;
                        ra0.z = -0.5f * ra0.z * ra0.z; ra0.w = -0.5f * ra0.w * ra0.w;
                        ra1.x = -0.5f * ra1.x * ra1.x; ra1.y = -0.5f * ra1.y * ra1.y;
                        ra1.z = -0.5f * ra1.z * ra1.z; ra1.w = -0.5f * ra1.w * ra1.w;
                    }
                    const float* pB = Bb + kk * TX_ + n0 + lbase;
                    rb0 = *(const float4*)pB;
                    rb1 = *(const float4*)(pB + 4);
                }
                *(float4*)&As[0][kRow][lbase]     = ra0;
                *(float4*)&As[0][kRow][lbase + 4] = ra1;
                *(float4*)&Bs[0][kRow][lbase]     = rb0;
                *(float4*)&Bs[0][kRow][lbase + 4] = rb1;
                HBAR(barid);

                const int NIT = K2_ / BK;   // 24
                for (int it = 0; it < NIT; ++it) {
                    const int cur = it & 1;
                    if (it + 1 < NIT) {
                        int kk = (it + 1) * BK + kRow;
                        int cA = (kk < C_) ? kk : kk - C_;
                        const float* pA = zpb + cA * TY_ + m0 + lbase;
                        ra0 = *(const float4*)pA;
                        ra1 = *(const float4*)(pA + 4);
                        if (kk < C_) {
                            ra0.x = -0.5f * ra0.x * ra0.x; ra0.y = -0.5f * ra0.y * ra0.y;
                            ra0.z = -0.5f * ra0.z * ra0.z; ra0.w = -0.5f * ra0.w * ra0.w;
                            ra1.x = -0.5f * ra1.x * ra1.x; ra1.y = -0.5f * ra1.y * ra1.y;
                            ra1.z = -0.5f * ra1.z * ra1.z; ra1.w = -0.5f * ra1.w * ra1.w;
                        }
                        const float* pB = Bb + kk * TX_ + n0 + lbase;
                        rb0 = *(const float4*)pB;
                        rb1 = *(const float4*)(pB + 4);
                    }
#pragma unroll
                    for (int k = 0; k < BK; k++) {
                        float4 a0 = *(const float4*)&As[cur][k][mBase];
                        float4 a1 = *(const float4*)&As[cur][k][mBase + 4];
                        float4 b0 = *(const float4*)&Bs[cur][k][nBase];
                        float4 b1 = *(const float4*)&Bs[cur][k][nBase + 4];
                        F2 bb[4];
                        bb[0].f = make_float2(b0.x, b0.y);
                        bb[1].f = make_float2(b0.z, b0.w);
                        bb[2].f = make_float2(b1.x, b1.y);
                        bb[3].f = make_float2(b1.z, b1.w);
                        float a[8] = {a0.x, a0.y, a0.z, a0.w, a1.x, a1.y, a1.z, a1.w};
#pragma unroll
                        for (int i = 0; i < 8; i++) {
                            F2 aa; aa.f = make_float2(a[i], a[i]);
#pragma unroll
                            for (int j = 0; j < 4; j++)
                                acc[i][j].u = ffma2(aa.u, bb[j].u, acc[i][j].u);
                        }
                    }
                    if (it + 1 < NIT) {
                        const int nxt = cur ^ 1;
                        *(float4*)&As[nxt][kRow][lbase]     = ra0;
                        *(float4*)&As[nxt][kRow][lbase + 4] = ra1;
                        *(float4*)&Bs[nxt][kRow][lbase]     = rb0;
                        *(float4*)&Bs[nxt][kRow][lbase + 4] = rb1;
                    }
                    HBAR(barid);
                }

                // epilogue: add per-column constant and store
                float4 cv0 = *(const float4*)(g_cvec + b * TX_ + n0 + nBase);
                float4 cv1 = *(const float4*)(g_cvec + b * TX_ + n0 + nBase + 4);
                float* outbase = g_negcent + ((size_t)b * TY_ + m0 + mBase) * TX_ + n0 + nBase;
#pragma unroll
                for (int i = 0; i < 8; i++) {
                    float4 o0, o1;
                    o0.x = acc[i][0].f.x + cv0.x; o0.y = acc[i][0].f.y + cv0.y;
                    o0.z = acc[i][1].f.x + cv0.z; o0.w = acc[i][1].f.y + cv0.w;
                    o1.x = acc[i][2].f.x + cv1.x; o1.y = acc[i][2].f.y + cv1.y;
                    o1.z = acc[i][3].f.x + cv1.z; o1.w = acc[i][3].f.y + cv1.w;
                    float* op = outbase + (size_t)i * TX_;
                    *(float4*)op       = o0;
                    *(float4*)(op + 4) = o1;
                }
                HBAR(barid);
            }

            // signal band completion for this tile (also for skipped tiles)
            if (htid == 0) {
                __threadfence();
                atomicAdd(&g_cnt[b * 16 + mblk], 1);
            }
        }
        return;
    }

    // ================= gated epilogue CTA: 32-row t-slice of attn + gathers =================
    {
        const int e    = bid - EPIS_;
        const int b    = e >> 6;                  // 64 CTAs per batch
        const int part = e & 63;
        const int t0   = part * 32;

        const int t_yb = min(y_lengths[b], TY_);
        int need = t_yb - t0;
        if (need < 1) need = 1;

        __shared__ int s_ready;
        if (tid == 0) {
            while (ld_acq(&g_btp[b]) < need) { }
            s_ready = 1;
        }
        __syncthreads();
        (void)s_ready;

        // attn: rows [t0, t0+32)
        {
            const int base = b * TY_ + t0;
#pragma unroll
            for (int i = 0; i < 8; i++) {
                int p   = tid + i * 512;              // 0..4095
                int t   = base + (p >> 7);
                int c4  = p & 127;
                int idx = g_idx[t];
                int s0  = c4 * 4;
                float4 val = make_float4(0.f, 0.f, 0.f, 0.f);
                if (idx >= s0 && idx < s0 + 4) {
                    if (idx == s0)          val.x = 1.f;
                    else if (idx == s0 + 1) val.y = 1.f;
                    else if (idx == s0 + 2) val.z = 1.f;
                    else                    val.w = 1.f;
                }
                *(float4*)(out_attn + (size_t)t * TX_ + s0) = val;
            }
        }

        // gather: all 192 channels, rows [t0, t0+32)  (6144 elements)
        {
#pragma unroll
            for (int i = 0; i < 12; i++) {
                int p  = tid + i * 512;
                int c  = p >> 5;
                int tl = p & 31;
                int t  = t0 + tl;
                int idx = g_idx[b * TY_ + t];
                float vm = 0.f, vl = 0.f;
                if (idx >= 0) {
                    int off = (b * C_ + c) * TX_ + idx;
                    vm = m_p[off];
                    vl = logs_p[off];
                }
                int o = (b * C_ + c) * TY_ + t;
                out_m[o] = vm;
                out_l[o] = vl;
            }
        }

        // cleanup: the 64th epilogue CTA of batch b resets per-batch flags for the next replay
        __syncthreads();
        if (tid == 0) {
            int old = atomicAdd(&g_epicnt[b], 1);
            if (old == 63) {
                g_prep[b] = 0;
                g_btp[b]  = 0;
                g_epicnt[b] = 0;
#pragma unroll
                for (int i = 0; i < 16; i++) g_cnt[b * 16 + i] = 0;
            }
        }
        return;
    }
}

// ---------------- launcher ----------------
extern "C" void kernel_launch(void* const* d_in, const int* in_sizes, int n_in,
                              void* d_out, int out_size)
{
    const float* z         = (const float*)d_in[0];
    const float* z_p       = (const float*)d_in[1];
    const float* m_p       = (const float*)d_in[2];
    const float* logs_p    = (const float*)d_in[3];
    const int*   x_lengths = (const int*)d_in[4];
    const int*   y_lengths = (const int*)d_in[5];
    const float* rand_u    = (const float*)d_in[6];

    float* out      = (float*)d_out;
    float* out_z    = out;                   // 16*192*32      = 98304
    float* out_ids  = out + 98304;           // 16
    float* out_attn = out + 98320;           // 16*2048*512    = 16777216
    float* out_m    = out + 16875536;        // 16*192*2048    = 6291456
    float* out_l    = out + 23166992;        // 16*192*2048    = 6291456
    (void)in_sizes; (void)n_in; (void)out_size;

    cudaFuncSetAttribute(fused_kernel, cudaFuncAttributeMaxDynamicSharedMemorySize, FUSED_SMEM);
    fused_kernel<<<NCTAS_, 512, FUSED_SMEM>>>(z_p, m_p, logs_p, z,
                                              x_lengths, y_lengths, rand_u,
                                              out_z, out_ids, out_attn, out_m, out_l);
}